// round 14
// baseline (speedup 1.0000x reference)
#include <cuda_runtime.h>
#include <cuda_fp16.h>
#include <math.h>

#define N_NODES 100000
#define N_EDGES 1600000
#define N_GRAPHS 64
#define D 128

// ---------------- scratch (no allocations allowed) ----------------
__device__ uint4 g_bufH16[N_NODES * 16];  // fp16 features (x norm_src): SpMM in / GEMM out
__device__ uint4 g_bufB16[N_NODES * 16];  // fp16 agg: SpMM out / GEMM in (layer4: pooled)
__device__ unsigned short g_Wh[5 * D * D]; // fp16 W transposed: [l][n][k]
__device__ float g_norm_src[N_NODES];
__device__ float g_norm_dst[N_NODES];
__device__ int   g_indeg[N_NODES];
__device__ int   g_outdeg[N_NODES];
__device__ int   g_rowstart[N_NODES];
__device__ int   g_cursor[N_NODES];      // running write ptr (init = rowstart)
__device__ int   g_col[N_EDGES];
__device__ float g_gsum[N_GRAPHS * D];
__device__ int   g_gcnt[N_GRAPHS];
__device__ int   g_ctr;

__device__ __forceinline__ unsigned packh2(float lo, float hi) {
    __half2 p = __floats2half2_rn(lo, hi);
    return *reinterpret_cast<unsigned*>(&p);
}

// ---------------- init: zero counters + convert weights (merged) ----------------
__global__ __launch_bounds__(256) void k_init(const float* W0, const float* W1,
                                              const float* W2, const float* W3,
                                              const float* W4) {
    int i = blockIdx.x * blockDim.x + threadIdx.x;
    int stride = gridDim.x * blockDim.x;
    for (int j = i; j < N_NODES; j += stride) {
        g_indeg[j] = 0; g_outdeg[j] = 0;
    }
    for (int j = i; j < N_GRAPHS * D; j += stride) g_gsum[j] = 0.f;
    if (i < N_GRAPHS) g_gcnt[i] = 0;
    if (i == 0) g_ctr = 0;
    // weights fp32 [k][n] -> fp16 transposed [n][k]
    const float* Wl[5] = {W0, W1, W2, W3, W4};
    for (int idx = i; idx < 5 * D * D; idx += stride) {
        int l = idx >> 14, rem = idx & (D * D - 1);
        int n = rem >> 7, k = rem & 127;
        __half v = __float2half_rn(Wl[l][k * D + n]);
        g_Wh[idx] = *reinterpret_cast<unsigned short*>(&v);
    }
}

__global__ __launch_bounds__(256) void k_deg(const int* __restrict__ src, const int* __restrict__ dst) {
    int t = blockIdx.x * blockDim.x + threadIdx.x;
    if (t >= N_EDGES / 4) return;
    int4 s = ((const int4*)src)[t];
    int4 d = ((const int4*)dst)[t];
    atomicAdd(&g_outdeg[s.x], 1); atomicAdd(&g_outdeg[s.y], 1);
    atomicAdd(&g_outdeg[s.z], 1); atomicAdd(&g_outdeg[s.w], 1);
    atomicAdd(&g_indeg[d.x], 1);  atomicAdd(&g_indeg[d.y], 1);
    atomicAdd(&g_indeg[d.z], 1);  atomicAdd(&g_indeg[d.w], 1);
}

// norms + CSR row-start reservation (cursor := rowstart) + input convert.
__global__ __launch_bounds__(256) void k_norm_cvt(const float* __restrict__ h) {
    int t = blockIdx.x * blockDim.x + threadIdx.x;
    if (t < N_NODES) {
        int od = g_outdeg[t], id = g_indeg[t];
        g_norm_src[t] = rsqrtf((float)(od > 1 ? od : 1));
        g_norm_dst[t] = rsqrtf((float)(id > 1 ? id : 1));
        int rs = atomicAdd(&g_ctr, id);
        g_rowstart[t] = rs;
        g_cursor[t]   = rs;
    }
    if (t < N_NODES * 32) {           // one float4 -> one uint2 (fp16 x norm_src)
        int od = g_outdeg[t >> 5];
        float ns = rsqrtf((float)(od > 1 ? od : 1));
        float4 v = ((const float4*)h)[t];
        uint2 o;
        o.x = packh2(v.x * ns, v.y * ns);
        o.y = packh2(v.z * ns, v.w * ns);
        ((uint2*)g_bufH16)[t] = o;
    }
}

// single atomic per edge: cursor already holds the absolute write position
__global__ __launch_bounds__(256) void k_fill(const int* __restrict__ src, const int* __restrict__ dst) {
    int t = blockIdx.x * blockDim.x + threadIdx.x;
    if (t >= N_EDGES / 4) return;
    int4 s = ((const int4*)src)[t];
    int4 d = ((const int4*)dst)[t];
    int p0 = atomicAdd(&g_cursor[d.x], 1);
    int p1 = atomicAdd(&g_cursor[d.y], 1);
    int p2 = atomicAdd(&g_cursor[d.z], 1);
    int p3 = atomicAdd(&g_cursor[d.w], 1);
    g_col[p0] = s.x;
    g_col[p1] = s.y;
    g_col[p2] = s.z;
    g_col[p3] = s.w;
}

// ---------------- SpMM (fp16 gather, native HADD2 accumulate):
// agg[i] = norm_dst[i] * sum_{e in row i} h16[col[e]]
__global__ __launch_bounds__(256) void k_spmm() {
    int gt = blockIdx.x * blockDim.x + threadIdx.x;
    int node = gt >> 5;
    int lane = gt & 31;
    if (node >= N_NODES) return;
    int eh  = lane >> 4;             // 0/1: which edge of the pair
    int sub = lane & 15;             // uint4 index within 256B row

    const uint4* __restrict__ hb = g_bufH16;
    const int start = g_rowstart[node];
    const int deg   = g_indeg[node];

    unsigned a0 = 0u, a1 = 0u, a2 = 0u, a3 = 0u;   // 4 half2 = 8 features

#define HACC(v) do { \
        asm("add.rn.f16x2 %0, %0, %1;" : "+r"(a0) : "r"((v).x)); \
        asm("add.rn.f16x2 %0, %0, %1;" : "+r"(a1) : "r"((v).y)); \
        asm("add.rn.f16x2 %0, %0, %1;" : "+r"(a2) : "r"((v).z)); \
        asm("add.rn.f16x2 %0, %0, %1;" : "+r"(a3) : "r"((v).w)); \
    } while (0)

    int e = 0;
    for (; e + 8 <= deg; e += 8) {            // 4 independent chains
        int cA = g_col[start + e + eh];
        int cB = g_col[start + e + 2 + eh];
        int cC = g_col[start + e + 4 + eh];
        int cD = g_col[start + e + 6 + eh];
        uint4 vA = hb[(size_t)cA * 16 + sub];
        uint4 vB = hb[(size_t)cB * 16 + sub];
        uint4 vC = hb[(size_t)cC * 16 + sub];
        uint4 vD = hb[(size_t)cD * 16 + sub];
        HACC(vA); HACC(vB); HACC(vC); HACC(vD);
    }
    for (; e + 2 <= deg; e += 2) {
        int c = g_col[start + e + eh];
        uint4 v = hb[(size_t)c * 16 + sub];
        HACC(v);
    }
    if (e < deg && eh == 0) {
        int c = g_col[start + e];
        uint4 v = hb[(size_t)c * 16 + sub];
        HACC(v);
    }
#undef HACC

    unsigned o;
    o = __shfl_xor_sync(0xffffffffu, a0, 16);
    asm("add.rn.f16x2 %0, %0, %1;" : "+r"(a0) : "r"(o));
    o = __shfl_xor_sync(0xffffffffu, a1, 16);
    asm("add.rn.f16x2 %0, %0, %1;" : "+r"(a1) : "r"(o));
    o = __shfl_xor_sync(0xffffffffu, a2, 16);
    asm("add.rn.f16x2 %0, %0, %1;" : "+r"(a2) : "r"(o));
    o = __shfl_xor_sync(0xffffffffu, a3, 16);
    asm("add.rn.f16x2 %0, %0, %1;" : "+r"(a3) : "r"(o));

    if (eh == 0) {
        unsigned nd2 = packh2(g_norm_dst[node], g_norm_dst[node]);
        uint4 w;
        asm("mul.rn.f16x2 %0, %1, %2;" : "=r"(w.x) : "r"(a0), "r"(nd2));
        asm("mul.rn.f16x2 %0, %1, %2;" : "=r"(w.y) : "r"(a1), "r"(nd2));
        asm("mul.rn.f16x2 %0, %1, %2;" : "=r"(w.z) : "r"(a2), "r"(nd2));
        asm("mul.rn.f16x2 %0, %1, %2;" : "=r"(w.w) : "r"(a3), "r"(nd2));
        g_bufB16[(size_t)node * 16 + sub] = w;
    }
}

// ---------------- GEMM (fp16 MMA): bufH16 = (bufB16 @ W + b) * norm_src
// 2 row-tiles of 128 per block; W loaded to smem once and reused.
#define BM 128
#define TILES_PER_BLK 2
#define AS_STRIDE 136
#define WS_STRIDE 136
#define WS_ELEMS (D * WS_STRIDE)
#define GEMM_SMEM ((WS_ELEMS + BM * AS_STRIDE) * 2)   // 69632 B

__global__ __launch_bounds__(256, 2) void k_gemm(const unsigned short* __restrict__ Wh,
                                                 const float* __restrict__ bias) {
    extern __shared__ __align__(16) unsigned short sm16[];
    unsigned short* Ws = sm16;               // [n=128][k stride 136]
    unsigned short* As = sm16 + WS_ELEMS;    // [m=128][k stride 136]
    int tid = threadIdx.x;
    int warp = tid >> 5, lane = tid & 31;
    int wm = (warp >> 2) * 64;
    int wn = (warp & 3) * 32;
    int qr = lane >> 2;
    int qc = lane & 3;

    const uint4* Wt4 = (const uint4*)Wh;     // 2048 uint4
#pragma unroll
    for (int i = 0; i < 8; i++) {
        int f = tid + i * 256;
        int n = f >> 4, k0 = (f & 15) * 8;
        *(uint4*)(Ws + n * WS_STRIDE + k0) = Wt4[f];
    }

    for (int tile = 0; tile < TILES_PER_BLK; tile++) {
        int row0 = (blockIdx.x * TILES_PER_BLK + tile) * BM;
#pragma unroll
        for (int i = 0; i < 8; i++) {
            int f = tid + i * 256;           // 2048 uint4 (16 per row)
            int r = f >> 4, c = f & 15;
            int grow = row0 + r;
            uint4 v = (grow < N_NODES) ? g_bufB16[(size_t)grow * 16 + c]
                                       : make_uint4(0u, 0u, 0u, 0u);
            *(uint4*)(As + r * AS_STRIDE + c * 8) = v;
        }
        __syncthreads();

        float c[4][4][4];
#pragma unroll
        for (int mt = 0; mt < 4; mt++)
#pragma unroll
            for (int nt = 0; nt < 4; nt++)
#pragma unroll
                for (int j = 0; j < 4; j++) c[mt][nt][j] = 0.f;

#pragma unroll
        for (int ks = 0; ks < 8; ks++) {
            int k0 = ks * 16;
            unsigned a[4][4];
#pragma unroll
            for (int mt = 0; mt < 4; mt++) {
                const unsigned short* base = As + (wm + mt * 16 + qr) * AS_STRIDE + k0 + 2 * qc;
                a[mt][0] = *(const unsigned*)(base);
                a[mt][1] = *(const unsigned*)(base + 8 * AS_STRIDE);
                a[mt][2] = *(const unsigned*)(base + 8);
                a[mt][3] = *(const unsigned*)(base + 8 * AS_STRIDE + 8);
            }
#pragma unroll
            for (int nt = 0; nt < 4; nt++) {
                const unsigned short* bb = Ws + (wn + nt * 8 + qr) * WS_STRIDE + k0 + 2 * qc;
                unsigned b0 = *(const unsigned*)(bb);
                unsigned b1 = *(const unsigned*)(bb + 8);
#pragma unroll
                for (int mt = 0; mt < 4; mt++) {
                    asm volatile(
                        "mma.sync.aligned.m16n8k16.row.col.f32.f16.f16.f32 "
                        "{%0,%1,%2,%3}, {%4,%5,%6,%7}, {%8,%9}, {%0,%1,%2,%3};"
                        : "+f"(c[mt][nt][0]), "+f"(c[mt][nt][1]),
                          "+f"(c[mt][nt][2]), "+f"(c[mt][nt][3])
                        : "r"(a[mt][0]), "r"(a[mt][1]), "r"(a[mt][2]), "r"(a[mt][3]),
                          "r"(b0), "r"(b1));
                }
            }
        }
        __syncthreads();   // all warps done reading As before next tile overwrites

        unsigned short* outb = (unsigned short*)g_bufH16;
#pragma unroll
        for (int mt = 0; mt < 4; mt++) {
            int r_lo = row0 + wm + mt * 16 + qr;
            int r_hi = r_lo + 8;
            float s_lo = (r_lo < N_NODES) ? g_norm_src[r_lo] : 0.f;
            float s_hi = (r_hi < N_NODES) ? g_norm_src[r_hi] : 0.f;
#pragma unroll
            for (int nt = 0; nt < 4; nt++) {
                int col = wn + nt * 8 + qc * 2;
                float2 bb = *(const float2*)(bias + col);
                if (r_lo < N_NODES)
                    *(unsigned*)(outb + (size_t)r_lo * D + col) =
                        packh2((c[mt][nt][0] + bb.x) * s_lo, (c[mt][nt][1] + bb.y) * s_lo);
                if (r_hi < N_NODES)
                    *(unsigned*)(outb + (size_t)r_hi * D + col) =
                        packh2((c[mt][nt][2] + bb.x) * s_hi, (c[mt][nt][3] + bb.y) * s_hi);
            }
        }
    }
}

// ---------------- mean-pool over layer-4 SpMM output (bufB16)
#define POOL_NODES 64
__global__ __launch_bounds__(128) void k_pool(const int* __restrict__ gid) {
    __shared__ int sg[POOL_NODES];
    int base = blockIdx.x * POOL_NODES;
    int tid = threadIdx.x;   // feature index
    for (int i = tid; i < POOL_NODES; i += 128) {
        int n = base + i;
        sg[i] = (n < N_NODES) ? gid[n] : -1;
    }
    __syncthreads();
    int nn = N_NODES - base; if (nn > POOL_NODES) nn = POOL_NODES;
    const unsigned short* h = (const unsigned short*)g_bufB16;

    float acc = 0.f;
    int cur = sg[0];
    int run = 0;
    for (int i = 0; i < nn; i++) {
        int g = sg[i];
        if (g != cur) {
            atomicAdd(&g_gsum[cur * D + tid], acc);
            if (tid == 0) atomicAdd(&g_gcnt[cur], run);
            acc = 0.f; run = 0; cur = g;
        }
        unsigned short u = h[(size_t)(base + i) * D + tid];
        acc += __half2float(*reinterpret_cast<__half*>(&u));
        run++;
    }
    atomicAdd(&g_gsum[cur * D + tid], acc);
    if (tid == 0) atomicAdd(&g_gcnt[cur], run);
}

// ---------------- head: hg = mean(agg) @ W5 + b5; out = sigmoid(hg . fc_w + fc_b)
// (affine map commutes with the per-graph mean)
__global__ __launch_bounds__(128) void k_head(const unsigned short* __restrict__ W5t, // [n][k] fp16
                                              const float* __restrict__ b5,
                                              const float* __restrict__ fcw,
                                              const float* __restrict__ fcb,
                                              float* __restrict__ out) {
    __shared__ float mean[128];
    __shared__ float red[128];
    int g = blockIdx.x;
    int tid = threadIdx.x;
    int c = g_gcnt[g];
    float inv = (c > 0) ? 1.f / (float)c : 0.f;
    mean[tid] = g_gsum[g * D + tid] * inv;
    __syncthreads();

    // hg[tid] = sum_k mean[k] * W5[k][tid] (+ b5[tid] unless empty graph)
    float acc = (c > 0) ? b5[tid] : 0.f;
    const unsigned short* wrow = W5t + tid * D;   // [n=tid][k]
#pragma unroll 16
    for (int k = 0; k < D; k++) {
        unsigned short u = wrow[k];
        acc += mean[k] * __half2float(*reinterpret_cast<const __half*>(&u));
    }
    red[tid] = acc * fcw[tid];
    __syncthreads();
#pragma unroll
    for (int s = 64; s > 0; s >>= 1) {
        if (tid < s) red[tid] += red[tid + s];
        __syncthreads();
    }
    if (tid == 0) {
        float x = red[0] + fcb[0];
        out[g] = 1.f / (1.f + expf(-x));
    }
}

// ---------------- launch ----------------
extern "C" void kernel_launch(void* const* d_in, const int* in_sizes, int n_in,
                              void* d_out, int out_size) {
    const float* h    = (const float*)d_in[0];
    const int*   src  = (const int*)  d_in[1];
    const int*   dst  = (const int*)  d_in[2];
    const int*   gid  = (const int*)  d_in[3];
    const float* W[5] = {(const float*)d_in[4],  (const float*)d_in[6],
                         (const float*)d_in[8],  (const float*)d_in[10],
                         (const float*)d_in[12]};
    const float* b[5] = {(const float*)d_in[5],  (const float*)d_in[7],
                         (const float*)d_in[9],  (const float*)d_in[11],
                         (const float*)d_in[13]};
    const float* fcw  = (const float*)d_in[14];
    const float* fcb  = (const float*)d_in[15];
    float* out = (float*)d_out;

    cudaFuncSetAttribute(k_gemm, cudaFuncAttributeMaxDynamicSharedMemorySize, GEMM_SMEM);

    unsigned short* Wh;
    cudaGetSymbolAddress((void**)&Wh, g_Wh);

    k_init<<<400, 256>>>(W[0], W[1], W[2], W[3], W[4]);
    k_deg <<<(N_EDGES / 4 + 255) / 256, 256>>>(src, dst);
    k_norm_cvt<<<(N_NODES * 32 + 255) / 256, 256>>>(h);
    k_fill<<<(N_EDGES / 4 + 255) / 256, 256>>>(src, dst);

    const int spmm_blocks = (N_NODES * 32) / 256;                       // 12500
    const int gemm_blocks = (N_NODES + BM * TILES_PER_BLK - 1) / (BM * TILES_PER_BLK); // 391

    for (int l = 0; l < 5; l++) {
        k_spmm<<<spmm_blocks, 256>>>();
        if (l < 4)
            k_gemm<<<gemm_blocks, 256, GEMM_SMEM>>>(Wh + l * D * D, b[l]);
    }

    k_pool<<<(N_NODES + POOL_NODES - 1) / POOL_NODES, 128>>>(gid);
    k_head<<<N_GRAPHS, 128>>>(Wh + 4 * D * D, b[4], fcw, fcb, out);
}